// round 14
// baseline (speedup 1.0000x reference)
#include <cuda_runtime.h>
#include <math.h>

#define DM 96
#define DI 192
#define DSN 16
#define RK 6
#define BB 2
#define LL 4096
#define CC 192
#define LT 4288
#define NC 32
#define CL 134
#define KSPLIT 32
#define KCHUNK 32
#define MTILE 16

typedef unsigned long long ull;

__device__ __forceinline__ ull pack2(float lo, float hi) {
    ull r; asm("mov.b64 %0, {%1, %2};" : "=l"(r) : "f"(lo), "f"(hi)); return r;
}
__device__ __forceinline__ ull fma2(ull a, ull b, ull c) {
    ull d; asm("fma.rn.f32x2 %0, %1, %2, %3;" : "=l"(d) : "l"(a), "l"(b), "l"(c)); return d;
}
__device__ __forceinline__ float2 unpack2(ull v) {
    float2 f; asm("mov.b64 {%0, %1}, %2;" : "=f"(f.x), "=f"(f.y) : "l"(v)); return f;
}

// ---------------- static scratch ----------------
__device__ __align__(16) float  g_wtA[DM * 2 * DI];   // [k][j]
__device__ __align__(16) float  g_wtO[DI * DM];       // [d][o]
__device__ __align__(16) float  g_xpT[DI * 40];       // x_proj_w [d][c] pad 40
__device__ __align__(16) float  g_wfcT[1024 * DI];    // depth_fc_w transposed [k][d]
__device__ __align__(16) float  g_An [DI * DSN];
__device__ __align__(16) float  g_x1 [BB * DI * LL];
__device__ __align__(16) float  g_xs [BB * DI * LT];
__device__ __align__(16) float  g_z  [BB * LL * DI];
__device__ __align__(16) float  g_dxc[BB * DI * 1024];
__device__ __align__(16) float  g_fcp[KSPLIT * BB * DI * DI];
__device__ __align__(16) float2 g_bc [BB * LT * DSN];
__device__ __align__(16) float2 g_q2 [BB * DI * LT];
__device__ __align__(16) float  g_yt [BB * LL * DI];
__device__ __align__(16) float  g_hend[BB * DI * NC * DSN];
__device__ __align__(16) float  g_P   [BB * DI * NC * DSN];

__device__ __forceinline__ float ex2(float x) {
    float r; asm("ex2.approx.ftz.f32 %0, %1;" : "=f"(r) : "f"(x)); return r;
}
__device__ __forceinline__ float silu_f(float v) {
    return __fdividef(v, 1.f + __expf(-v));
}

// ---------------- K0: weight transposes + A table + depth_fc transpose ----------------
__global__ void __launch_bounds__(256) k0_prep(const float* __restrict__ ipw,
                                               const float* __restrict__ opw,
                                               const float* __restrict__ alogs,
                                               const float* __restrict__ xpw,
                                               const float* __restrict__ wfc) {
    __shared__ float tile[32][33];
    if (blockIdx.x < 288) {
        int t = blockIdx.x * 256 + threadIdx.x;
        if (t < 2 * DI * DM) {
            int j = t / DM, k = t % DM;
            g_wtA[k * (2 * DI) + j] = ipw[t];
        }
        if (t < DM * DI) {
            int o = t / DI, d = t % DI;
            g_wtO[d * DM + o] = opw[t];
        }
        if (t < DI * DSN) g_An[t] = -expf(alogs[t]);
        if (t < DI * 40) {
            int d = t / 40, c = t % 40;
            g_xpT[t] = (c < 38) ? xpw[c * DI + d] : 0.f;
        }
    } else {
        int bb = blockIdx.x - 288;
        int kb = (bb & 31) * 32, db = (bb >> 5) * 32;
        int tx = threadIdx.x & 31, ty = threadIdx.x >> 5;
#pragma unroll
        for (int r = ty; r < 32; r += 8)
            tile[r][tx] = wfc[(size_t)(db + r) * 1024 + kb + tx];
        __syncthreads();
#pragma unroll
        for (int r = ty; r < 32; r += 8)
            g_wfcT[(size_t)(kb + r) * DI + db + tx] = tile[tx][r];
    }
}

// ---------------- K1: in_proj, 32-l tiles, 4j x 8l register blocking ----------------
__global__ void __launch_bounds__(384) k1_inproj(const float* __restrict__ x) {
    __shared__ __align__(16) float sbuf[32 * DI];
    float* xt = sbuf;
    float* zs = sbuf;
    int b  = blockIdx.y;
    int l0 = blockIdx.x * 32;
    int tid = threadIdx.x;

    const float4* xin = (const float4*)(x + ((size_t)b * LL + l0) * DM);
    for (int i = tid; i < 32 * 24; i += 384) {
        float4 v = xin[i];
        int l = i / 24, k4 = (i % 24) * 4;
        xt[(k4 + 0) * 36 + l] = v.x;
        xt[(k4 + 1) * 36 + l] = v.y;
        xt[(k4 + 2) * 36 + l] = v.z;
        xt[(k4 + 3) * 36 + l] = v.w;
    }
    __syncthreads();

    int jq = tid % 96;
    int lo = tid / 96;
    int j0 = jq * 4;
    const float* xrow = xt + lo * 8;

    ull acc2[4][4];
#pragma unroll
    for (int i = 0; i < 4; i++)
#pragma unroll
        for (int p = 0; p < 4; p++) acc2[i][p] = 0ull;

#pragma unroll 4
    for (int k = 0; k < 96; k++) {
        float4 wv = *(const float4*)(g_wtA + k * 384 + j0);
        ull w0 = pack2(wv.x, wv.x), w1 = pack2(wv.y, wv.y);
        ull w2 = pack2(wv.z, wv.z), w3 = pack2(wv.w, wv.w);
        ulonglong2 xa = *(const ulonglong2*)(xrow + k * 36);
        ulonglong2 xb = *(const ulonglong2*)(xrow + k * 36 + 4);
        acc2[0][0] = fma2(xa.x, w0, acc2[0][0]); acc2[0][1] = fma2(xa.y, w0, acc2[0][1]);
        acc2[0][2] = fma2(xb.x, w0, acc2[0][2]); acc2[0][3] = fma2(xb.y, w0, acc2[0][3]);
        acc2[1][0] = fma2(xa.x, w1, acc2[1][0]); acc2[1][1] = fma2(xa.y, w1, acc2[1][1]);
        acc2[1][2] = fma2(xb.x, w1, acc2[1][2]); acc2[1][3] = fma2(xb.y, w1, acc2[1][3]);
        acc2[2][0] = fma2(xa.x, w2, acc2[2][0]); acc2[2][1] = fma2(xa.y, w2, acc2[2][1]);
        acc2[2][2] = fma2(xb.x, w2, acc2[2][2]); acc2[2][3] = fma2(xb.y, w2, acc2[2][3]);
        acc2[3][0] = fma2(xa.x, w3, acc2[3][0]); acc2[3][1] = fma2(xa.y, w3, acc2[3][1]);
        acc2[3][2] = fma2(xb.x, w3, acc2[3][2]); acc2[3][3] = fma2(xb.y, w3, acc2[3][3]);
    }
    __syncthreads();

    if (j0 < DI) {
#pragma unroll
        for (int jj = 0; jj < 4; jj++) {
            float* dst = g_x1 + ((size_t)b * DI + j0 + jj) * LL + l0 + lo * 8;
            float2 a0 = unpack2(acc2[jj][0]), a1 = unpack2(acc2[jj][1]);
            float2 a2 = unpack2(acc2[jj][2]), a3 = unpack2(acc2[jj][3]);
            *(float4*)dst       = make_float4(a0.x, a0.y, a1.x, a1.y);
            *(float4*)(dst + 4) = make_float4(a2.x, a2.y, a3.x, a3.y);
        }
    } else {
        int d0 = j0 - DI;
#pragma unroll
        for (int jj = 0; jj < 4; jj++) {
#pragma unroll
            for (int p = 0; p < 4; p++) {
                float2 v = unpack2(acc2[jj][p]);
                zs[(lo * 8 + 2 * p + 0) * DI + d0 + jj] = v.x;
                zs[(lo * 8 + 2 * p + 1) * DI + d0 + jj] = v.y;
            }
        }
    }
    __syncthreads();
    float4* zdst = (float4*)(g_z + ((size_t)b * LL + l0) * DI);
    const float4* zsrc = (const float4*)zs;
#pragma unroll
    for (int r = 0; r < 4; r++) zdst[tid + 384 * r] = zsrc[tid + 384 * r];
}

// ---------------- K23: fused depthwise convs, plane split into 2 halves ----------------
__global__ void __launch_bounds__(256) k23_conv(const float* __restrict__ cw1,
                                                const float* __restrict__ cb1,
                                                const float* __restrict__ cw2,
                                                const float* __restrict__ cb2) {
    __shared__ __align__(16) float s_in [36 * 64];
    __shared__ __align__(16) float s_mid[34 * 64];
    __shared__ float w1[9], w2[9], bb1, bb2;
    int plane = blockIdx.x >> 1;
    int half  = blockIdx.x & 1;
    int h0 = half * 32;
    int c = plane % DI;
    int tid = threadIdx.x;
    if (tid < 9)        w1[tid]     = cw1[c * 9 + tid];
    else if (tid < 18)  w2[tid - 9] = cw2[c * 9 + tid - 9];
    else if (tid == 18) bb1 = cb1[c];
    else if (tid == 19) bb2 = cb2[c];

    const float* src = g_x1 + (size_t)plane * LL;
    for (int i = tid; i < 576; i += 256) {
        int r = i >> 4, c4 = i & 15;
        int gr = h0 - 2 + r;
        float4 v = make_float4(0.f, 0.f, 0.f, 0.f);
        if (gr >= 0 && gr < 64) v = *(const float4*)(src + gr * 64 + c4 * 4);
        *(float4*)&s_in[r * 64 + c4 * 4] = v;
    }
    __syncthreads();

    int w = tid & 63, q = tid >> 6;
    float* dst1 = g_xs + (size_t)plane * LT + CC;
    int wl = (w > 0) ? 1 : 0, wr = (w < 63) ? 1 : 0;
    for (int r = 0; r < 9; r++) {
        int mi = q * 9 + r;
        if (mi >= 34) break;
        int gm = h0 - 1 + mi;
        float val = 0.f;
        if (gm >= 0 && gm < 64) {
            float s = bb1;
#pragma unroll
            for (int kh = 0; kh < 3; kh++) {
                const float* row = s_in + (mi + kh) * 64 + w;
                float acc = w1[kh * 3 + 1] * row[0];
                if (wl) acc += w1[kh * 3 + 0] * row[-1];
                if (wr) acc += w1[kh * 3 + 2] * row[1];
                s += acc;
            }
            val = silu_f(s);
            if (gm >= h0 && gm < h0 + 32)
                dst1[gm * 64 + w] = val;
        }
        s_mid[mi * 64 + w] = val;
    }
    __syncthreads();

    int ow = tid & 31;
    int oq = tid >> 5;
    float* dst2 = g_dxc + (size_t)plane * 1024;
#pragma unroll
    for (int r = 0; r < 2; r++) {
        int ohl = oq * 2 + r;
        int oh  = half * 16 + ohl;
        float s = bb2;
#pragma unroll
        for (int kh = 0; kh < 3; kh++) {
            const float* mrow = s_mid + (2 * ohl + kh) * 64;
#pragma unroll
            for (int kw = 0; kw < 3; kw++) {
                int iw = 2 * ow + kw - 1;
                if (iw < 0 || iw >= 64) continue;
                s += w2[kh * 3 + kw] * mrow[iw];
            }
        }
        dst2[oh * 32 + ow] = s;
    }
}

// ---------------- K4a: depth_fc K-split GEMM (KSPLIT=32, register prefetch) ----------------
__global__ void __launch_bounds__(192) k4a_fc() {
    __shared__ __align__(16) float sXt[KCHUNK * 20];    // [k][m]
    __shared__ __align__(16) float sWt[16 * 196];       // [k][d]
    int m0 = blockIdx.x * MTILE;
    int ks = blockIdx.y;
    int k0 = ks * KCHUNK;
    int tid = threadIdx.x;
    int dq = tid % 48, mq = tid / 48;

    if (tid < MTILE * (KCHUNK / 4)) {    // 128 items
        int m = tid >> 3, c4 = tid & 7;
        float4 v = *(const float4*)(g_dxc + (size_t)(m0 + m) * 1024 + k0 + c4 * 4);
        sXt[(c4 * 4 + 0) * 20 + m] = v.x;
        sXt[(c4 * 4 + 1) * 20 + m] = v.y;
        sXt[(c4 * 4 + 2) * 20 + m] = v.z;
        sXt[(c4 * 4 + 3) * 20 + m] = v.w;
    }

    ull acc2[4][2];
#pragma unroll
    for (int i = 0; i < 4; i++) { acc2[i][0] = 0ull; acc2[i][1] = 0ull; }

#pragma unroll
    for (int s = 0; s < KCHUNK / 16; s++) {
        __syncthreads();
#pragma unroll
        for (int j = 0; j < 4; j++) {
            int q4 = tid + 192 * j;
            int row = q4 / 48, col = q4 % 48;
            float4 v = *(const float4*)(g_wfcT + (size_t)(k0 + s * 16 + row) * DI + col * 4);
            *(float4*)&sWt[row * 196 + col * 4] = v;
        }
        __syncthreads();
        // register-prefetched inner loop
        ulonglong2 wc = *(const ulonglong2*)&sWt[0 * 196 + dq * 4];
        float4     xc = *(const float4*)&sXt[(s * 16 + 0) * 20 + mq * 4];
#pragma unroll
        for (int k = 0; k < 16; k++) {
            ulonglong2 wn;
            float4 xn;
            if (k < 15) {
                wn = *(const ulonglong2*)&sWt[(k + 1) * 196 + dq * 4];
                xn = *(const float4*)&sXt[(s * 16 + k + 1) * 20 + mq * 4];
            }
            ull xm0 = pack2(xc.x, xc.x);
            ull xm1 = pack2(xc.y, xc.y);
            ull xm2 = pack2(xc.z, xc.z);
            ull xm3 = pack2(xc.w, xc.w);
            acc2[0][0] = fma2(wc.x, xm0, acc2[0][0]); acc2[0][1] = fma2(wc.y, xm0, acc2[0][1]);
            acc2[1][0] = fma2(wc.x, xm1, acc2[1][0]); acc2[1][1] = fma2(wc.y, xm1, acc2[1][1]);
            acc2[2][0] = fma2(wc.x, xm2, acc2[2][0]); acc2[2][1] = fma2(wc.y, xm2, acc2[2][1]);
            acc2[3][0] = fma2(wc.x, xm3, acc2[3][0]); acc2[3][1] = fma2(wc.y, xm3, acc2[3][1]);
            if (k < 15) { wc = wn; xc = xn; }
        }
    }

    float* pb = g_fcp + ((size_t)ks * BB * DI + m0 + mq * 4) * DI + dq * 4;
#pragma unroll
    for (int m = 0; m < 4; m++) {
        float2 a = unpack2(acc2[m][0]);
        float2 bq = unpack2(acc2[m][1]);
        *(float4*)(pb + (size_t)m * DI) = make_float4(a.x, a.y, bq.x, bq.y);
    }
}

// ---------------- K4b: reduce 32 partials + bias + SiLU ----------------
__global__ void __launch_bounds__(192) k4b_fc(const float* __restrict__ fcb) {
    int m = blockIdx.x;
    int d = threadIdx.x;
    int b = m / DI, lp = m % DI;
    float s = fcb[d];
    const float* p = g_fcp + (size_t)m * DI + d;
#pragma unroll
    for (int ks = 0; ks < KSPLIT; ks++) {
        s += p[(size_t)ks * BB * DI * DI];
    }
    g_xs[((size_t)b * DI + d) * LT + lp] = silu_f(s);
}

// ---------------- K5: x_proj + dt proj + softplus ----------------
__global__ void __launch_bounds__(256) k5_xproj(const float* __restrict__ dtw,
                                                const float* __restrict__ dtb) {
    __shared__ __align__(16) float s_u[DI * 32];
    __shared__ __align__(16) float sxd[38 * 36];
    __shared__ __align__(16) float s_dtw[DI * RK];
    __shared__ float s_dtb[DI];
    int tid = threadIdx.x;
    int b   = blockIdx.y;
    int l0  = blockIdx.x * 32;

    for (int i = tid; i < DI * 8; i += 256) {
        int d = i >> 3, c4 = i & 7;
        ((float4*)s_u)[d * 8 + c4] =
            *(const float4*)(g_xs + ((size_t)b * DI + d) * LT + l0 + c4 * 4);
    }
    for (int i = tid; i < DI * RK; i += 256) s_dtw[i] = dtw[i];
    if (tid < DI) s_dtb[tid] = dtb[tid];
    __syncthreads();

    if (tid < 152) {
        int cp = tid >> 3, lq = tid & 7;
        int c0 = 2 * cp;
        ull a0 = 0ull, a1 = 0ull, b0 = 0ull, b1 = 0ull;
#pragma unroll 4
        for (int d = 0; d < DI; d++) {
            ulonglong2 uv = *(const ulonglong2*)&s_u[d * 32 + lq * 4];
            ull xp2 = *(const ull*)&g_xpT[d * 40 + c0];
            float2 xf = unpack2(xp2);
            ull x0p = pack2(xf.x, xf.x), x1p = pack2(xf.y, xf.y);
            a0 = fma2(uv.x, x0p, a0); a1 = fma2(uv.y, x0p, a1);
            b0 = fma2(uv.x, x1p, b0); b1 = fma2(uv.y, x1p, b1);
        }
        float2 r0 = unpack2(a0), r1 = unpack2(a1);
        *(float4*)&sxd[c0 * 36 + lq * 4] = make_float4(r0.x, r0.y, r1.x, r1.y);
        float2 s0 = unpack2(b0), s1 = unpack2(b1);
        *(float4*)&sxd[(c0 + 1) * 36 + lq * 4] = make_float4(s0.x, s0.y, s1.x, s1.y);
    }
    __syncthreads();

    {
        int n = tid & 15;
        int lh = tid >> 4;
        if (lh < 16) {
#pragma unroll
            for (int rr = 0; rr < 2; rr++) {
                int l = lh + rr * 16;
                g_bc[((size_t)b * LT + l0 + l) * DSN + n] =
                    make_float2(sxd[(RK + n) * 36 + l], sxd[(RK + DSN + n) * 36 + l]);
            }
        }
    }

    const float L2E = 1.4426950408889634f;
    for (int item = tid; item < DI * 8; item += 256) {
        int d = item >> 3, lq = item & 7;
        float dt0 = s_dtb[d], dt1 = dt0, dt2 = dt0, dt3 = dt0;
#pragma unroll
        for (int r = 0; r < RK; r++) {
            float w = s_dtw[d * RK + r];
            float4 xv = *(const float4*)&sxd[r * 36 + lq * 4];
            dt0 += w * xv.x; dt1 += w * xv.y; dt2 += w * xv.z; dt3 += w * xv.w;
        }
        float del[4]; float dts[4] = {dt0, dt1, dt2, dt3};
#pragma unroll
        for (int j = 0; j < 4; j++) {
            float dt = dts[j];
            if (dt > 20.f)       del[j] = dt;
            else if (dt < -20.f) del[j] = __expf(dt);
            else                 del[j] = log1pf(__expf(dt));
        }
        float4 uv = *(const float4*)&s_u[d * 32 + lq * 4];
        float2* qd = g_q2 + ((size_t)b * DI + d) * LT + l0 + lq * 4;
        *(float4*)qd       = make_float4(del[0] * L2E, del[0] * uv.x, del[1] * L2E, del[1] * uv.y);
        *(float4*)(qd + 2) = make_float4(del[2] * L2E, del[2] * uv.z, del[3] * L2E, del[3] * uv.w);
    }
}

// ---------------- K6: chunked scan, 2 n-states per thread (128 threads) ----------------
__global__ void __launch_bounds__(128) k6_phaseA() {
    __shared__ __align__(16) float2 s_bc[CL][DSN];
    int dg = blockIdx.x % 12;
    int c  = blockIdx.x / 12;
    int b  = blockIdx.y;
    int t  = threadIdx.x;
    int l0 = c * CL;

    {
        const float4* src = (const float4*)(g_bc + ((size_t)b * LT + l0) * DSN);
        float4* dst = (float4*)&s_bc[0][0];
        for (int i = t; i < CL * DSN / 2; i += 128) dst[i] = src[i];
    }
    __syncthreads();

    int w = t >> 5, lane = t & 31;
    int dgrp = lane >> 3, n = lane & 7;
    int d = dg * 16 + w * 4 + dgrp;
    int g = b * DI + d;
    float An0 = g_An[d * DSN + n];
    float An1 = g_An[d * DSN + n + 8];
    const float2* qrow = g_q2 + (size_t)g * LT + l0;
    float h0 = 0.f, P0 = 1.f, h1 = 0.f, P1 = 1.f;
#pragma unroll 2
    for (int l = 0; l < CL; l++) {
        float2 qq = __ldg(&qrow[l]);
        float2 bv0 = s_bc[l][n];
        float2 bv1 = s_bc[l][n + 8];
        float a0 = ex2(qq.x * An0);
        float a1 = ex2(qq.x * An1);
        P0 *= a0; h0 = a0 * h0 + qq.y * bv0.x;
        P1 *= a1; h1 = a1 * h1 + qq.y * bv1.x;
    }
    int idx = (g * NC + c) * DSN + n;
    g_hend[idx]     = h0; g_P[idx]     = P0;
    g_hend[idx + 8] = h1; g_P[idx + 8] = P1;
}

__global__ void __launch_bounds__(128) k6_phaseC(const float* __restrict__ dsv) {
    __shared__ __align__(16) float2 s_bc[CL][DSN];
    __shared__ __align__(16) float  s_y[CL][16];
    int dg = blockIdx.x % 12;
    int c  = blockIdx.x / 12;
    int b  = blockIdx.y;
    int t  = threadIdx.x;
    int l0 = c * CL;

    {
        int dl = t >> 3, j = t & 7;
        int gq = b * DI + dg * 16 + dl;
        float ds = dsv[dg * 16 + dl];
        const float* us = g_xs + (size_t)gq * LT + l0;
        for (int k = j; k < CL; k += 8) s_y[k][dl] = ds * us[k];
    }
    {
        const float4* src = (const float4*)(g_bc + ((size_t)b * LT + l0) * DSN);
        float4* dst = (float4*)&s_bc[0][0];
        for (int i = t; i < CL * DSN / 2; i += 128) dst[i] = src[i];
    }

    int w = t >> 5, lane = t & 31;
    int dgrp = lane >> 3, n = lane & 7;
    int dw = w * 4 + dgrp;
    int d  = dg * 16 + dw;
    int g  = b * DI + d;

    float h0 = 0.f, h1 = 0.f;
    for (int cc = 0; cc < c; cc++) {
        int idx = (g * NC + cc) * DSN + n;
        h0 = g_P[idx]     * h0 + g_hend[idx];
        h1 = g_P[idx + 8] * h1 + g_hend[idx + 8];
    }
    float An0 = g_An[d * DSN + n];
    float An1 = g_An[d * DSN + n + 8];
    const float2* qrow = g_q2 + (size_t)g * LT + l0;
    __syncthreads();

#pragma unroll 2
    for (int l = 0; l < CL; l++) {
        float2 qq = __ldg(&qrow[l]);
        float2 bv0 = s_bc[l][n];
        float2 bv1 = s_bc[l][n + 8];
        float a0 = ex2(qq.x * An0);
        float a1 = ex2(qq.x * An1);
        h0 = a0 * h0 + qq.y * bv0.x;
        h1 = a1 * h1 + qq.y * bv1.x;
        float pr = h0 * bv0.y + h1 * bv1.y;
        pr += __shfl_xor_sync(0xffffffffu, pr, 1);
        pr += __shfl_xor_sync(0xffffffffu, pr, 2);
        pr += __shfl_xor_sync(0xffffffffu, pr, 4);
        if (n == 0) s_y[l][dw] += pr;
    }
    __syncthreads();

    for (int i = t; i < CL * 4; i += 128) {
        int l = i >> 2, q4 = i & 3;
        int lg = l0 + l;
        if (lg >= CC) {
            float4 v = *(const float4*)&s_y[l][q4 * 4];
            *(float4*)(g_yt + ((size_t)b * LL + (lg - CC)) * DI + dg * 16 + q4 * 4) = v;
        }
    }
}

// ---------------- K7: LN + gate + out_proj ----------------
__global__ void __launch_bounds__(192) k7_out(const float* __restrict__ onw,
                                              const float* __restrict__ onb,
                                              float* __restrict__ out) {
    __shared__ __align__(16) float sy [8 * DI];
    __shared__ __align__(16) float sgv[DI * 10];
    __shared__ __align__(16) float2 sr2[3][48][8];
    __shared__ float smu[8], srs[8];
    int b   = blockIdx.y;
    int l0  = blockIdx.x * 8;
    int tid = threadIdx.x;
    int lane = tid & 31, w = tid >> 5;

    const float4* ysrc = (const float4*)(g_yt + ((size_t)b * LL + l0) * DI);
    float4* syd = (float4*)sy;
#pragma unroll
    for (int i = 0; i < 2; i++) syd[tid + 192 * i] = ysrc[tid + 192 * i];
    __syncthreads();

#pragma unroll
    for (int pass = 0; pass < 2; pass++) {
        int l = pass * 6 + w;
        if (l < 8) {
            float s1 = 0.f, s2 = 0.f;
#pragma unroll
            for (int k = 0; k < 6; k++) {
                float v = sy[l * DI + lane + 32 * k];
                s1 += v; s2 += v * v;
            }
#pragma unroll
            for (int o = 16; o > 0; o >>= 1) {
                s1 += __shfl_xor_sync(0xffffffffu, s1, o);
                s2 += __shfl_xor_sync(0xffffffffu, s2, o);
            }
            if (lane == 0) {
                float mu = s1 * (1.f / 192.f);
                smu[l] = mu;
                srs[l] = rsqrtf(s2 * (1.f / 192.f) - mu * mu + 1e-5f);
            }
        }
    }
    __syncthreads();

    float wn = onw[tid], bn = onb[tid];
    const float* zr = g_z + ((size_t)b * LL + l0) * DI + tid;
#pragma unroll
    for (int l = 0; l < 8; l++) {
        float y  = sy[l * DI + tid];
        float yn = (y - smu[l]) * srs[l] * wn + bn;
        float zv = zr[(size_t)l * DI];
        sgv[tid * 10 + l] = yn * silu_f(zv);
    }
    __syncthreads();

    int oo = tid % 48, q = tid / 48;
    int o0 = oo * 2;
    int dbase = q * 48;
    ull acc2[2][4] = {{0ull,0ull,0ull,0ull},{0ull,0ull,0ull,0ull}};
#pragma unroll 4
    for (int i = 0; i < 48; i++) {
        int d = dbase + i;
        float2 wf = *(const float2*)&g_wtO[d * DM + o0];
        ull w0 = pack2(wf.x, wf.x), w1 = pack2(wf.y, wf.y);
        const ull* gp = (const ull*)&sgv[d * 10];
        acc2[0][0] = fma2(gp[0], w0, acc2[0][0]);
        acc2[0][1] = fma2(gp[1], w0, acc2[0][1]);
        acc2[0][2] = fma2(gp[2], w0, acc2[0][2]);
        acc2[0][3] = fma2(gp[3], w0, acc2[0][3]);
        acc2[1][0] = fma2(gp[0], w1, acc2[1][0]);
        acc2[1][1] = fma2(gp[1], w1, acc2[1][1]);
        acc2[1][2] = fma2(gp[2], w1, acc2[1][2]);
        acc2[1][3] = fma2(gp[3], w1, acc2[1][3]);
    }
    if (q > 0) {
#pragma unroll
        for (int p = 0; p < 4; p++) {
            float2 a = unpack2(acc2[0][p]);
            float2 bq = unpack2(acc2[1][p]);
            sr2[q - 1][oo][2 * p + 0] = make_float2(a.x, bq.x);
            sr2[q - 1][oo][2 * p + 1] = make_float2(a.y, bq.y);
        }
    }
    __syncthreads();
    if (q == 0) {
#pragma unroll
        for (int p = 0; p < 4; p++) {
            float2 a = unpack2(acc2[0][p]);
            float2 bq = unpack2(acc2[1][p]);
            float2 r0 = make_float2(a.x, bq.x);
            float2 r1 = make_float2(a.y, bq.y);
#pragma unroll
            for (int qq = 0; qq < 3; qq++) {
                float2 s0 = sr2[qq][oo][2 * p + 0];
                float2 s1 = sr2[qq][oo][2 * p + 1];
                r0.x += s0.x; r0.y += s0.y;
                r1.x += s1.x; r1.y += s1.y;
            }
            *(float2*)&out[((size_t)b * LL + l0 + 2 * p + 0) * DM + o0] = r0;
            *(float2*)&out[((size_t)b * LL + l0 + 2 * p + 1) * DM + o0] = r1;
        }
    }
}

// ---------------- launch ----------------
extern "C" void kernel_launch(void* const* d_in, const int* in_sizes, int n_in,
                              void* d_out, int out_size) {
    const float* x            = (const float*)d_in[0];
    const float* in_proj_w    = (const float*)d_in[1];
    const float* conv2d_w     = (const float*)d_in[2];
    const float* conv2d_b     = (const float*)d_in[3];
    const float* depth_conv_w = (const float*)d_in[4];
    const float* depth_conv_b = (const float*)d_in[5];
    const float* depth_fc_w   = (const float*)d_in[6];
    const float* depth_fc_b   = (const float*)d_in[7];
    const float* x_proj_w     = (const float*)d_in[8];
    const float* dt_projs_w   = (const float*)d_in[9];
    const float* dt_projs_b   = (const float*)d_in[10];
    const float* A_logs       = (const float*)d_in[11];
    const float* Ds           = (const float*)d_in[12];
    const float* out_norm_w   = (const float*)d_in[13];
    const float* out_norm_b   = (const float*)d_in[14];
    const float* out_proj_w   = (const float*)d_in[15];
    float* out = (float*)d_out;

    k0_prep<<<480, 256>>>(in_proj_w, out_proj_w, A_logs, x_proj_w, depth_fc_w);
    k1_inproj<<<dim3(LL / 32, BB), 384>>>(x);
    k23_conv<<<BB * DI * 2, 256>>>(conv2d_w, conv2d_b, depth_conv_w, depth_conv_b);
    k4a_fc<<<dim3(BB * DI / MTILE, KSPLIT), 192>>>();
    k4b_fc<<<BB * DI, 192>>>(depth_fc_b);
    k5_xproj<<<dim3(LT / 32, BB), 256>>>(dt_projs_w, dt_projs_b);
    k6_phaseA<<<dim3(12 * NC, BB), 128>>>();
    k6_phaseC<<<dim3(12 * NC, BB), 128>>>(Ds);
    k7_out<<<dim3(LL / 8, BB), 192>>>(out_norm_w, out_norm_b, out);
}

// round 15
// speedup vs baseline: 1.0199x; 1.0199x over previous
#include <cuda_runtime.h>
#include <math.h>

#define DM 96
#define DI 192
#define DSN 16
#define RK 6
#define BB 2
#define LL 4096
#define CC 192
#define LT 4288
#define NC 32
#define CL 134
#define KSPLIT 32
#define KCHUNK 32
#define MTILE 16

typedef unsigned long long ull;

__device__ __forceinline__ ull pack2(float lo, float hi) {
    ull r; asm("mov.b64 %0, {%1, %2};" : "=l"(r) : "f"(lo), "f"(hi)); return r;
}
__device__ __forceinline__ ull fma2(ull a, ull b, ull c) {
    ull d; asm("fma.rn.f32x2 %0, %1, %2, %3;" : "=l"(d) : "l"(a), "l"(b), "l"(c)); return d;
}
__device__ __forceinline__ float2 unpack2(ull v) {
    float2 f; asm("mov.b64 {%0, %1}, %2;" : "=f"(f.x), "=f"(f.y) : "l"(v)); return f;
}

// ---------------- static scratch ----------------
__device__ __align__(16) float  g_wtA[DM * 2 * DI];   // [k][j]
__device__ __align__(16) float  g_wtO[DI * DM];       // [d][o]
__device__ __align__(16) float  g_xpT[DI * 40];       // x_proj_w [d][c] pad 40
__device__ __align__(16) float  g_wfcT[1024 * DI];    // depth_fc_w transposed [k][d]
__device__ __align__(16) float  g_An [DI * DSN];
__device__ __align__(16) float  g_x1 [BB * DI * LL];
__device__ __align__(16) float  g_xs [BB * DI * LT];
__device__ __align__(16) float  g_z  [BB * LL * DI];
__device__ __align__(16) float  g_dxc[BB * DI * 1024];
__device__ __align__(16) float  g_fcp[KSPLIT * BB * DI * DI];
__device__ __align__(16) float2 g_bc [BB * LT * DSN];
__device__ __align__(16) float2 g_q2 [BB * DI * LT];
__device__ __align__(16) float  g_yt [BB * LL * DI];
__device__ __align__(16) float  g_hend[BB * DI * NC * DSN];
__device__ __align__(16) float  g_P   [BB * DI * NC * DSN];
__device__ int g_flag[BB * 12 * NC];                  // decoupled-lookback flags

__device__ __forceinline__ float ex2(float x) {
    float r; asm("ex2.approx.ftz.f32 %0, %1;" : "=f"(r) : "f"(x)); return r;
}
__device__ __forceinline__ float silu_f(float v) {
    return __fdividef(v, 1.f + __expf(-v));
}

// ---------------- K0: weight transposes + A table + depth_fc transpose + flag zero ----------------
__global__ void __launch_bounds__(256) k0_prep(const float* __restrict__ ipw,
                                               const float* __restrict__ opw,
                                               const float* __restrict__ alogs,
                                               const float* __restrict__ xpw,
                                               const float* __restrict__ wfc) {
    __shared__ float tile[32][33];
    if (blockIdx.x < 288) {
        int t = blockIdx.x * 256 + threadIdx.x;
        if (t < BB * 12 * NC) g_flag[t] = 0;
        if (t < 2 * DI * DM) {
            int j = t / DM, k = t % DM;
            g_wtA[k * (2 * DI) + j] = ipw[t];
        }
        if (t < DM * DI) {
            int o = t / DI, d = t % DI;
            g_wtO[d * DM + o] = opw[t];
        }
        if (t < DI * DSN) g_An[t] = -expf(alogs[t]);
        if (t < DI * 40) {
            int d = t / 40, c = t % 40;
            g_xpT[t] = (c < 38) ? xpw[c * DI + d] : 0.f;
        }
    } else {
        int bb = blockIdx.x - 288;
        int kb = (bb & 31) * 32, db = (bb >> 5) * 32;
        int tx = threadIdx.x & 31, ty = threadIdx.x >> 5;
#pragma unroll
        for (int r = ty; r < 32; r += 8)
            tile[r][tx] = wfc[(size_t)(db + r) * 1024 + kb + tx];
        __syncthreads();
#pragma unroll
        for (int r = ty; r < 32; r += 8)
            g_wfcT[(size_t)(kb + r) * DI + db + tx] = tile[tx][r];
    }
}

// ---------------- K1: in_proj, 32-l tiles, 4j x 8l register blocking ----------------
__global__ void __launch_bounds__(384) k1_inproj(const float* __restrict__ x) {
    __shared__ __align__(16) float sbuf[32 * DI];
    float* xt = sbuf;
    float* zs = sbuf;
    int b  = blockIdx.y;
    int l0 = blockIdx.x * 32;
    int tid = threadIdx.x;

    const float4* xin = (const float4*)(x + ((size_t)b * LL + l0) * DM);
    for (int i = tid; i < 32 * 24; i += 384) {
        float4 v = xin[i];
        int l = i / 24, k4 = (i % 24) * 4;
        xt[(k4 + 0) * 36 + l] = v.x;
        xt[(k4 + 1) * 36 + l] = v.y;
        xt[(k4 + 2) * 36 + l] = v.z;
        xt[(k4 + 3) * 36 + l] = v.w;
    }
    __syncthreads();

    int jq = tid % 96;
    int lo = tid / 96;
    int j0 = jq * 4;
    const float* xrow = xt + lo * 8;

    ull acc2[4][4];
#pragma unroll
    for (int i = 0; i < 4; i++)
#pragma unroll
        for (int p = 0; p < 4; p++) acc2[i][p] = 0ull;

#pragma unroll 4
    for (int k = 0; k < 96; k++) {
        float4 wv = *(const float4*)(g_wtA + k * 384 + j0);
        ull w0 = pack2(wv.x, wv.x), w1 = pack2(wv.y, wv.y);
        ull w2 = pack2(wv.z, wv.z), w3 = pack2(wv.w, wv.w);
        ulonglong2 xa = *(const ulonglong2*)(xrow + k * 36);
        ulonglong2 xb = *(const ulonglong2*)(xrow + k * 36 + 4);
        acc2[0][0] = fma2(xa.x, w0, acc2[0][0]); acc2[0][1] = fma2(xa.y, w0, acc2[0][1]);
        acc2[0][2] = fma2(xb.x, w0, acc2[0][2]); acc2[0][3] = fma2(xb.y, w0, acc2[0][3]);
        acc2[1][0] = fma2(xa.x, w1, acc2[1][0]); acc2[1][1] = fma2(xa.y, w1, acc2[1][1]);
        acc2[1][2] = fma2(xb.x, w1, acc2[1][2]); acc2[1][3] = fma2(xb.y, w1, acc2[1][3]);
        acc2[2][0] = fma2(xa.x, w2, acc2[2][0]); acc2[2][1] = fma2(xa.y, w2, acc2[2][1]);
        acc2[2][2] = fma2(xb.x, w2, acc2[2][2]); acc2[2][3] = fma2(xb.y, w2, acc2[2][3]);
        acc2[3][0] = fma2(xa.x, w3, acc2[3][0]); acc2[3][1] = fma2(xa.y, w3, acc2[3][1]);
        acc2[3][2] = fma2(xb.x, w3, acc2[3][2]); acc2[3][3] = fma2(xb.y, w3, acc2[3][3]);
    }
    __syncthreads();

    if (j0 < DI) {
#pragma unroll
        for (int jj = 0; jj < 4; jj++) {
            float* dst = g_x1 + ((size_t)b * DI + j0 + jj) * LL + l0 + lo * 8;
            float2 a0 = unpack2(acc2[jj][0]), a1 = unpack2(acc2[jj][1]);
            float2 a2 = unpack2(acc2[jj][2]), a3 = unpack2(acc2[jj][3]);
            *(float4*)dst       = make_float4(a0.x, a0.y, a1.x, a1.y);
            *(float4*)(dst + 4) = make_float4(a2.x, a2.y, a3.x, a3.y);
        }
    } else {
        int d0 = j0 - DI;
#pragma unroll
        for (int jj = 0; jj < 4; jj++) {
#pragma unroll
            for (int p = 0; p < 4; p++) {
                float2 v = unpack2(acc2[jj][p]);
                zs[(lo * 8 + 2 * p + 0) * DI + d0 + jj] = v.x;
                zs[(lo * 8 + 2 * p + 1) * DI + d0 + jj] = v.y;
            }
        }
    }
    __syncthreads();
    float4* zdst = (float4*)(g_z + ((size_t)b * LL + l0) * DI);
    const float4* zsrc = (const float4*)zs;
#pragma unroll
    for (int r = 0; r < 4; r++) zdst[tid + 384 * r] = zsrc[tid + 384 * r];
}

// ---------------- K23: fused depthwise convs, plane split into 2 halves ----------------
__global__ void __launch_bounds__(256) k23_conv(const float* __restrict__ cw1,
                                                const float* __restrict__ cb1,
                                                const float* __restrict__ cw2,
                                                const float* __restrict__ cb2) {
    __shared__ __align__(16) float s_in [36 * 64];
    __shared__ __align__(16) float s_mid[34 * 64];
    __shared__ float w1[9], w2[9], bb1, bb2;
    int plane = blockIdx.x >> 1;
    int half  = blockIdx.x & 1;
    int h0 = half * 32;
    int c = plane % DI;
    int tid = threadIdx.x;
    if (tid < 9)        w1[tid]     = cw1[c * 9 + tid];
    else if (tid < 18)  w2[tid - 9] = cw2[c * 9 + tid - 9];
    else if (tid == 18) bb1 = cb1[c];
    else if (tid == 19) bb2 = cb2[c];

    const float* src = g_x1 + (size_t)plane * LL;
    for (int i = tid; i < 576; i += 256) {
        int r = i >> 4, c4 = i & 15;
        int gr = h0 - 2 + r;
        float4 v = make_float4(0.f, 0.f, 0.f, 0.f);
        if (gr >= 0 && gr < 64) v = *(const float4*)(src + gr * 64 + c4 * 4);
        *(float4*)&s_in[r * 64 + c4 * 4] = v;
    }
    __syncthreads();

    int w = tid & 63, q = tid >> 6;
    float* dst1 = g_xs + (size_t)plane * LT + CC;
    int wl = (w > 0) ? 1 : 0, wr = (w < 63) ? 1 : 0;
    for (int r = 0; r < 9; r++) {
        int mi = q * 9 + r;
        if (mi >= 34) break;
        int gm = h0 - 1 + mi;
        float val = 0.f;
        if (gm >= 0 && gm < 64) {
            float s = bb1;
#pragma unroll
            for (int kh = 0; kh < 3; kh++) {
                const float* row = s_in + (mi + kh) * 64 + w;
                float acc = w1[kh * 3 + 1] * row[0];
                if (wl) acc += w1[kh * 3 + 0] * row[-1];
                if (wr) acc += w1[kh * 3 + 2] * row[1];
                s += acc;
            }
            val = silu_f(s);
            if (gm >= h0 && gm < h0 + 32)
                dst1[gm * 64 + w] = val;
        }
        s_mid[mi * 64 + w] = val;
    }
    __syncthreads();

    int ow = tid & 31;
    int oq = tid >> 5;
    float* dst2 = g_dxc + (size_t)plane * 1024;
#pragma unroll
    for (int r = 0; r < 2; r++) {
        int ohl = oq * 2 + r;
        int oh  = half * 16 + ohl;
        float s = bb2;
#pragma unroll
        for (int kh = 0; kh < 3; kh++) {
            const float* mrow = s_mid + (2 * ohl + kh) * 64;
#pragma unroll
            for (int kw = 0; kw < 3; kw++) {
                int iw = 2 * ow + kw - 1;
                if (iw < 0 || iw >= 64) continue;
                s += w2[kh * 3 + kw] * mrow[iw];
            }
        }
        dst2[oh * 32 + ow] = s;
    }
}

// ---------------- K4a: depth_fc K-split GEMM (frozen) ----------------
__global__ void __launch_bounds__(192) k4a_fc() {
    __shared__ __align__(16) float sXt[KCHUNK * 20];
    __shared__ __align__(16) float sWt[16 * 196];
    int m0 = blockIdx.x * MTILE;
    int ks = blockIdx.y;
    int k0 = ks * KCHUNK;
    int tid = threadIdx.x;
    int dq = tid % 48, mq = tid / 48;

    if (tid < MTILE * (KCHUNK / 4)) {
        int m = tid >> 3, c4 = tid & 7;
        float4 v = *(const float4*)(g_dxc + (size_t)(m0 + m) * 1024 + k0 + c4 * 4);
        sXt[(c4 * 4 + 0) * 20 + m] = v.x;
        sXt[(c4 * 4 + 1) * 20 + m] = v.y;
        sXt[(c4 * 4 + 2) * 20 + m] = v.z;
        sXt[(c4 * 4 + 3) * 20 + m] = v.w;
    }

    ull acc2[4][2];
#pragma unroll
    for (int i = 0; i < 4; i++) { acc2[i][0] = 0ull; acc2[i][1] = 0ull; }

#pragma unroll
    for (int s = 0; s < KCHUNK / 16; s++) {
        __syncthreads();
#pragma unroll
        for (int j = 0; j < 4; j++) {
            int q4 = tid + 192 * j;
            int row = q4 / 48, col = q4 % 48;
            float4 v = *(const float4*)(g_wfcT + (size_t)(k0 + s * 16 + row) * DI + col * 4);
            *(float4*)&sWt[row * 196 + col * 4] = v;
        }
        __syncthreads();
        ulonglong2 wc = *(const ulonglong2*)&sWt[0 * 196 + dq * 4];
        float4     xc = *(const float4*)&sXt[(s * 16 + 0) * 20 + mq * 4];
#pragma unroll
        for (int k = 0; k < 16; k++) {
            ulonglong2 wn;
            float4 xn;
            if (k < 15) {
                wn = *(const ulonglong2*)&sWt[(k + 1) * 196 + dq * 4];
                xn = *(const float4*)&sXt[(s * 16 + k + 1) * 20 + mq * 4];
            }
            ull xm0 = pack2(xc.x, xc.x);
            ull xm1 = pack2(xc.y, xc.y);
            ull xm2 = pack2(xc.z, xc.z);
            ull xm3 = pack2(xc.w, xc.w);
            acc2[0][0] = fma2(wc.x, xm0, acc2[0][0]); acc2[0][1] = fma2(wc.y, xm0, acc2[0][1]);
            acc2[1][0] = fma2(wc.x, xm1, acc2[1][0]); acc2[1][1] = fma2(wc.y, xm1, acc2[1][1]);
            acc2[2][0] = fma2(wc.x, xm2, acc2[2][0]); acc2[2][1] = fma2(wc.y, xm2, acc2[2][1]);
            acc2[3][0] = fma2(wc.x, xm3, acc2[3][0]); acc2[3][1] = fma2(wc.y, xm3, acc2[3][1]);
            if (k < 15) { wc = wn; xc = xn; }
        }
    }

    float* pb = g_fcp + ((size_t)ks * BB * DI + m0 + mq * 4) * DI + dq * 4;
#pragma unroll
    for (int m = 0; m < 4; m++) {
        float2 a = unpack2(acc2[m][0]);
        float2 bq = unpack2(acc2[m][1]);
        *(float4*)(pb + (size_t)m * DI) = make_float4(a.x, a.y, bq.x, bq.y);
    }
}

// ---------------- K4b: reduce 32 partials + bias + SiLU ----------------
__global__ void __launch_bounds__(192) k4b_fc(const float* __restrict__ fcb) {
    int m = blockIdx.x;
    int d = threadIdx.x;
    int b = m / DI, lp = m % DI;
    float s = fcb[d];
    const float* p = g_fcp + (size_t)m * DI + d;
#pragma unroll
    for (int ks = 0; ks < KSPLIT; ks++) {
        s += p[(size_t)ks * BB * DI * DI];
    }
    g_xs[((size_t)b * DI + d) * LT + lp] = silu_f(s);
}

// ---------------- K5: x_proj + dt proj + softplus ----------------
__global__ void __launch_bounds__(256) k5_xproj(const float* __restrict__ dtw,
                                                const float* __restrict__ dtb) {
    __shared__ __align__(16) float s_u[DI * 32];
    __shared__ __align__(16) float sxd[38 * 36];
    __shared__ __align__(16) float s_dtw[DI * RK];
    __shared__ float s_dtb[DI];
    int tid = threadIdx.x;
    int b   = blockIdx.y;
    int l0  = blockIdx.x * 32;

    for (int i = tid; i < DI * 8; i += 256) {
        int d = i >> 3, c4 = i & 7;
        ((float4*)s_u)[d * 8 + c4] =
            *(const float4*)(g_xs + ((size_t)b * DI + d) * LT + l0 + c4 * 4);
    }
    for (int i = tid; i < DI * RK; i += 256) s_dtw[i] = dtw[i];
    if (tid < DI) s_dtb[tid] = dtb[tid];
    __syncthreads();

    if (tid < 152) {
        int cp = tid >> 3, lq = tid & 7;
        int c0 = 2 * cp;
        ull a0 = 0ull, a1 = 0ull, b0 = 0ull, b1 = 0ull;
#pragma unroll 4
        for (int d = 0; d < DI; d++) {
            ulonglong2 uv = *(const ulonglong2*)&s_u[d * 32 + lq * 4];
            ull xp2 = *(const ull*)&g_xpT[d * 40 + c0];
            float2 xf = unpack2(xp2);
            ull x0p = pack2(xf.x, xf.x), x1p = pack2(xf.y, xf.y);
            a0 = fma2(uv.x, x0p, a0); a1 = fma2(uv.y, x0p, a1);
            b0 = fma2(uv.x, x1p, b0); b1 = fma2(uv.y, x1p, b1);
        }
        float2 r0 = unpack2(a0), r1 = unpack2(a1);
        *(float4*)&sxd[c0 * 36 + lq * 4] = make_float4(r0.x, r0.y, r1.x, r1.y);
        float2 s0 = unpack2(b0), s1 = unpack2(b1);
        *(float4*)&sxd[(c0 + 1) * 36 + lq * 4] = make_float4(s0.x, s0.y, s1.x, s1.y);
    }
    __syncthreads();

    {
        int n = tid & 15;
        int lh = tid >> 4;
        if (lh < 16) {
#pragma unroll
            for (int rr = 0; rr < 2; rr++) {
                int l = lh + rr * 16;
                g_bc[((size_t)b * LT + l0 + l) * DSN + n] =
                    make_float2(sxd[(RK + n) * 36 + l], sxd[(RK + DSN + n) * 36 + l]);
            }
        }
    }

    const float L2E = 1.4426950408889634f;
    for (int item = tid; item < DI * 8; item += 256) {
        int d = item >> 3, lq = item & 7;
        float dt0 = s_dtb[d], dt1 = dt0, dt2 = dt0, dt3 = dt0;
#pragma unroll
        for (int r = 0; r < RK; r++) {
            float w = s_dtw[d * RK + r];
            float4 xv = *(const float4*)&sxd[r * 36 + lq * 4];
            dt0 += w * xv.x; dt1 += w * xv.y; dt2 += w * xv.z; dt3 += w * xv.w;
        }
        float del[4]; float dts[4] = {dt0, dt1, dt2, dt3};
#pragma unroll
        for (int j = 0; j < 4; j++) {
            float dt = dts[j];
            if (dt > 20.f)       del[j] = dt;
            else if (dt < -20.f) del[j] = __expf(dt);
            else                 del[j] = log1pf(__expf(dt));
        }
        float4 uv = *(const float4*)&s_u[d * 32 + lq * 4];
        float2* qd = g_q2 + ((size_t)b * DI + d) * LT + l0 + lq * 4;
        *(float4*)qd       = make_float4(del[0] * L2E, del[0] * uv.x, del[1] * L2E, del[1] * uv.y);
        *(float4*)(qd + 2) = make_float4(del[2] * L2E, del[2] * uv.z, del[3] * L2E, del[3] * uv.w);
    }
}

// ---------------- K6: fused scan with decoupled lookback ----------------
// grid (12*NC, BB), 128 threads. smem 34.3KB -> 6 blocks/SM -> 888 slots >= 768 blocks
// (whole grid co-resident; spin-wait cannot deadlock).
__global__ void __launch_bounds__(128) k6_scan(const float* __restrict__ dsv) {
    __shared__ __align__(16) float2 s_q[16][CL];     // 17152 B
    __shared__ __align__(16) float2 s_bc[CL][DSN];   // 17152 B
    int dg = blockIdx.x % 12;
    int c  = blockIdx.x / 12;
    int b  = blockIdx.y;
    int t  = threadIdx.x;
    int l0 = c * CL;

    {   // stage q rows: 16 d-rows, 8 threads each
        int dl = t >> 3, j = t & 7;
        const float2* src = g_q2 + (size_t)(b * DI + dg * 16 + dl) * LT + l0;
        for (int k = j; k < CL; k += 8) s_q[dl][k] = src[k];
    }
    {   // stage bc tile
        const float4* src = (const float4*)(g_bc + ((size_t)b * LT + l0) * DSN);
        float4* dst = (float4*)&s_bc[0][0];
        for (int i = t; i < CL * DSN / 2; i += 128) dst[i] = src[i];
    }
    __syncthreads();

    int w = t >> 5, lane = t & 31;
    int dgrp = lane >> 3, n = lane & 7;
    int dw = w * 4 + dgrp;
    int d  = dg * 16 + dw;
    int g  = b * DI + d;
    float An0 = g_An[d * DSN + n];
    float An1 = g_An[d * DSN + n + 8];

    // ---- pass 1: local aggregates ----
    float h0 = 0.f, P0 = 1.f, h1 = 0.f, P1 = 1.f;
#pragma unroll 2
    for (int l = 0; l < CL; l++) {
        float2 qq = s_q[dw][l];
        float bx = s_bc[l][n].x;
        float b1x = s_bc[l][n + 8].x;
        float a0 = ex2(qq.x * An0);
        float a1 = ex2(qq.x * An1);
        P0 *= a0; h0 = a0 * h0 + qq.y * bx;
        P1 *= a1; h1 = a1 * h1 + qq.y * b1x;
    }
    int idx = (g * NC + c) * DSN + n;
    g_hend[idx]     = h0; g_P[idx]     = P0;
    g_hend[idx + 8] = h1; g_P[idx + 8] = P1;
    __threadfence();
    __syncthreads();
    int fbase = (b * 12 + dg) * NC;
    if (t == 0) atomicExch(&g_flag[fbase + c], 1);

    // ---- lookback ----
    float hp0 = 0.f, hp1 = 0.f;
    if (c > 0) {
        if (t == 0) {
            volatile int* vf = g_flag;
            for (int cc = 0; cc < c; cc++)
                while (vf[fbase + cc] == 0) { }
        }
        __syncthreads();
        for (int cc = 0; cc < c; cc++) {
            int ix = (g * NC + cc) * DSN + n;
            hp0 = __ldcg(&g_P[ix])     * hp0 + __ldcg(&g_hend[ix]);
            hp1 = __ldcg(&g_P[ix + 8]) * hp1 + __ldcg(&g_hend[ix + 8]);
        }
    }

    // ---- pass 2: outputs ----
    float ds = dsv[d];
    const float* urow = g_xs + (size_t)g * LT + l0;
    h0 = hp0; h1 = hp1;
#pragma unroll 2
    for (int l = 0; l < CL; l++) {
        float2 qq = s_q[dw][l];
        float2 bv0 = s_bc[l][n];
        float2 bv1 = s_bc[l][n + 8];
        float a0 = ex2(qq.x * An0);
        float a1 = ex2(qq.x * An1);
        h0 = a0 * h0 + qq.y * bv0.x;
        h1 = a1 * h1 + qq.y * bv1.x;
        float pr = h0 * bv0.y + h1 * bv1.y;
        pr += __shfl_xor_sync(0xffffffffu, pr, 1);
        pr += __shfl_xor_sync(0xffffffffu, pr, 2);
        pr += __shfl_xor_sync(0xffffffffu, pr, 4);
        int lg = l0 + l;
        if (n == 0 && lg >= CC) {
            g_yt[((size_t)b * LL + (lg - CC)) * DI + d] = pr + ds * urow[l];
        }
    }
}

// ---------------- K7: LN + gate + out_proj ----------------
__global__ void __launch_bounds__(192) k7_out(const float* __restrict__ onw,
                                              const float* __restrict__ onb,
                                              float* __restrict__ out) {
    __shared__ __align__(16) float sy [8 * DI];
    __shared__ __align__(16) float sgv[DI * 10];
    __shared__ __align__(16) float2 sr2[3][48][8];
    __shared__ float smu[8], srs[8];
    int b   = blockIdx.y;
    int l0  = blockIdx.x * 8;
    int tid = threadIdx.x;
    int lane = tid & 31, w = tid >> 5;

    const float4* ysrc = (const float4*)(g_yt + ((size_t)b * LL + l0) * DI);
    float4* syd = (float4*)sy;
#pragma unroll
    for (int i = 0; i < 2; i++) syd[tid + 192 * i] = ysrc[tid + 192 * i];
    __syncthreads();

#pragma unroll
    for (int pass = 0; pass < 2; pass++) {
        int l = pass * 6 + w;
        if (l < 8) {
            float s1 = 0.f, s2 = 0.f;
#pragma unroll
            for (int k = 0; k < 6; k++) {
                float v = sy[l * DI + lane + 32 * k];
                s1 += v; s2 += v * v;
            }
#pragma unroll
            for (int o = 16; o > 0; o >>= 1) {
                s1 += __shfl_xor_sync(0xffffffffu, s1, o);
                s2 += __shfl_xor_sync(0xffffffffu, s2, o);
            }
            if (lane == 0) {
                float mu = s1 * (1.f / 192.f);
                smu[l] = mu;
                srs[l] = rsqrtf(s2 * (1.f / 192.f) - mu * mu + 1e-5f);
            }
        }
    }
    __syncthreads();

    float wn = onw[tid], bn = onb[tid];
    const float* zr = g_z + ((size_t)b * LL + l0) * DI + tid;
#pragma unroll
    for (int l = 0; l < 8; l++) {
        float y  = sy[l * DI + tid];
        float yn = (y - smu[l]) * srs[l] * wn + bn;
        float zv = zr[(size_t)l * DI];
        sgv[tid * 10 + l] = yn * silu_f(zv);
    }
    __syncthreads();

    int oo = tid % 48, q = tid / 48;
    int o0 = oo * 2;
    int dbase = q * 48;
    ull acc2[2][4] = {{0ull,0ull,0ull,0ull},{0ull,0ull,0ull,0ull}};
#pragma unroll 4
    for (int i = 0; i < 48; i++) {
        int d = dbase + i;
        float2 wf = *(const float2*)&g_wtO[d * DM + o0];
        ull w0 = pack2(wf.x, wf.x), w1 = pack2(wf.y, wf.y);
        const ull* gp = (const ull*)&sgv[d * 10];
        acc2[0][0] = fma2(gp[0], w0, acc2[0][0]);
        acc2[0][1] = fma2(gp[1], w0, acc2[0][1]);
        acc2[0][2] = fma2(gp[2], w0, acc2[0][2]);
        acc2[0][3] = fma2(gp[3], w0, acc2[0][3]);
        acc2[1][0] = fma2(gp[0], w1, acc2[1][0]);
        acc2[1][1] = fma2(gp[1], w1, acc2[1][1]);
        acc2[1][2] = fma2(gp[2], w1, acc2[1][2]);
        acc2[1][3] = fma2(gp[3], w1, acc2[1][3]);
    }
    if (q > 0) {
#pragma unroll
        for (int p = 0; p < 4; p++) {
            float2 a = unpack2(acc2[0][p]);
            float2 bq = unpack2(acc2[1][p]);
            sr2[q - 1][oo][2 * p + 0] = make_float2(a.x, bq.x);
            sr2[q - 1][oo][2 * p + 1] = make_float2(a.y, bq.y);
        }
    }
    __syncthreads();
    if (q == 0) {
#pragma unroll
        for (int p = 0; p < 4; p++) {
            float2 a = unpack2(acc2[0][p]);
            float2 bq = unpack2(acc2[1][p]);
            float2 r0 = make_float2(a.x, bq.x);
            float2 r1 = make_float2(a.y, bq.y);
#pragma unroll
            for (int qq = 0; qq < 3; qq++) {
                float2 s0 = sr2[qq][oo][2 * p + 0];
                float2 s1 = sr2[qq][oo][2 * p + 1];
                r0.x += s0.x; r0.y += s0.y;
                r1.x += s1.x; r1.y += s1.y;
            }
            *(float2*)&out[((size_t)b * LL + l0 + 2 * p + 0) * DM + o0] = r0;
            *(float2*)&out[((size_t)b * LL + l0 + 2 * p + 1) * DM + o0] = r1;
        }
    }
}

// ---------------- launch ----------------
extern "C" void kernel_launch(void* const* d_in, const int* in_sizes, int n_in,
                              void* d_out, int out_size) {
    const float* x            = (const float*)d_in[0];
    const float* in_proj_w    = (const float*)d_in[1];
    const float* conv2d_w     = (const float*)d_in[2];
    const float* conv2d_b     = (const float*)d_in[3];
    const float* depth_conv_w = (const float*)d_in[4];
    const float* depth_conv_b = (const float*)d_in[5];
    const float* depth_fc_w   = (const float*)d_in[6];
    const float* depth_fc_b   = (const float*)d_in[7];
    const float* x_proj_w     = (const float*)d_in[8];
    const float* dt_projs_w   = (const float*)d_in[9];
    const float* dt_projs_b   = (const float*)d_in[10];
    const float* A_logs       = (const float*)d_in[11];
    const float* Ds           = (const float*)d_in[12];
    const float* out_norm_w   = (const float*)d_in[13];
    const float* out_norm_b   = (const float*)d_in[14];
    const float* out_proj_w   = (const float*)d_in[15];
    float* out = (float*)d_out;

    k0_prep<<<480, 256>>>(in_proj_w, out_proj_w, A_logs, x_proj_w, depth_fc_w);
    k1_inproj<<<dim3(LL / 32, BB), 384>>>(x);
    k23_conv<<<BB * DI * 2, 256>>>(conv2d_w, conv2d_b, depth_conv_w, depth_conv_b);
    k4a_fc<<<dim3(BB * DI / MTILE, KSPLIT), 192>>>();
    k4b_fc<<<BB * DI, 192>>>(depth_fc_b);
    k5_xproj<<<dim3(LT / 32, BB), 256>>>(dt_projs_w, dt_projs_b);
    k6_scan<<<dim3(12 * NC, BB), 128>>>(Ds);
    k7_out<<<dim3(LL / 8, BB), 192>>>(out_norm_w, out_norm_b, out);
}

// round 16
// speedup vs baseline: 1.0358x; 1.0156x over previous
#include <cuda_runtime.h>
#include <math.h>

#define DM 96
#define DI 192
#define DSN 16
#define RK 6
#define BB 2
#define LL 4096
#define CC 192
#define LT 4288
#define NC 32
#define CL 134
#define KSPLIT 32
#define KCHUNK 32
#define MTILE 16

typedef unsigned long long ull;

__device__ __forceinline__ ull pack2(float lo, float hi) {
    ull r; asm("mov.b64 %0, {%1, %2};" : "=l"(r) : "f"(lo), "f"(hi)); return r;
}
__device__ __forceinline__ ull fma2(ull a, ull b, ull c) {
    ull d; asm("fma.rn.f32x2 %0, %1, %2, %3;" : "=l"(d) : "l"(a), "l"(b), "l"(c)); return d;
}
__device__ __forceinline__ float2 unpack2(ull v) {
    float2 f; asm("mov.b64 {%0, %1}, %2;" : "=f"(f.x), "=f"(f.y) : "l"(v)); return f;
}

// ---------------- static scratch ----------------
__device__ __align__(16) float  g_wtA[DM * 2 * DI];   // [k][j]
__device__ __align__(16) float  g_wtO[DI * DM];       // [d][o]
__device__ __align__(16) float  g_xpT[DI * 40];       // x_proj_w [d][c] pad 40
__device__ __align__(16) float  g_wfcT[1024 * DI];    // depth_fc_w transposed [k][d]
__device__ __align__(16) float  g_An [DI * DSN];
__device__ __align__(16) float  g_x1 [BB * DI * LL];
__device__ __align__(16) float  g_xs [BB * DI * LT];
__device__ __align__(16) float  g_z  [BB * LL * DI];
__device__ __align__(16) float  g_dxc[BB * DI * 1024];
__device__ __align__(16) float  g_fcp[KSPLIT * BB * DI * DI];
__device__ __align__(16) float2 g_bc [BB * LT * DSN];
__device__ __align__(16) float2 g_q2 [BB * DI * LT];
__device__ __align__(16) float  g_yt [BB * LL * DI];
__device__ __align__(16) float  g_hend[BB * DI * NC * DSN];
__device__ __align__(16) float  g_P   [BB * DI * NC * DSN];
__device__ int g_flag[BB * 12 * NC];                  // decoupled-lookback flags

__device__ __forceinline__ float ex2(float x) {
    float r; asm("ex2.approx.ftz.f32 %0, %1;" : "=f"(r) : "f"(x)); return r;
}
__device__ __forceinline__ float silu_f(float v) {
    return __fdividef(v, 1.f + __expf(-v));
}

// ---------------- K0: weight transposes + A table + depth_fc transpose + flag zero ----------------
__global__ void __launch_bounds__(256) k0_prep(const float* __restrict__ ipw,
                                               const float* __restrict__ opw,
                                               const float* __restrict__ alogs,
                                               const float* __restrict__ xpw,
                                               const float* __restrict__ wfc) {
    __shared__ float tile[32][33];
    if (blockIdx.x < 288) {
        int t = blockIdx.x * 256 + threadIdx.x;
        if (t < BB * 12 * NC) g_flag[t] = 0;
        if (t < 2 * DI * DM) {
            int j = t / DM, k = t % DM;
            g_wtA[k * (2 * DI) + j] = ipw[t];
        }
        if (t < DM * DI) {
            int o = t / DI, d = t % DI;
            g_wtO[d * DM + o] = opw[t];
        }
        if (t < DI * DSN) g_An[t] = -expf(alogs[t]);
        if (t < DI * 40) {
            int d = t / 40, c = t % 40;
            g_xpT[t] = (c < 38) ? xpw[c * DI + d] : 0.f;
        }
    } else {
        int bb = blockIdx.x - 288;
        int kb = (bb & 31) * 32, db = (bb >> 5) * 32;
        int tx = threadIdx.x & 31, ty = threadIdx.x >> 5;
#pragma unroll
        for (int r = ty; r < 32; r += 8)
            tile[r][tx] = wfc[(size_t)(db + r) * 1024 + kb + tx];
        __syncthreads();
#pragma unroll
        for (int r = ty; r < 32; r += 8)
            g_wfcT[(size_t)(kb + r) * DI + db + tx] = tile[tx][r];
    }
}

// ---------------- K1: in_proj, 32-l tiles, 4j x 8l register blocking ----------------
__global__ void __launch_bounds__(384) k1_inproj(const float* __restrict__ x) {
    __shared__ __align__(16) float sbuf[32 * DI];
    float* xt = sbuf;
    float* zs = sbuf;
    int b  = blockIdx.y;
    int l0 = blockIdx.x * 32;
    int tid = threadIdx.x;

    const float4* xin = (const float4*)(x + ((size_t)b * LL + l0) * DM);
    for (int i = tid; i < 32 * 24; i += 384) {
        float4 v = xin[i];
        int l = i / 24, k4 = (i % 24) * 4;
        xt[(k4 + 0) * 36 + l] = v.x;
        xt[(k4 + 1) * 36 + l] = v.y;
        xt[(k4 + 2) * 36 + l] = v.z;
        xt[(k4 + 3) * 36 + l] = v.w;
    }
    __syncthreads();

    int jq = tid % 96;
    int lo = tid / 96;
    int j0 = jq * 4;
    const float* xrow = xt + lo * 8;

    ull acc2[4][4];
#pragma unroll
    for (int i = 0; i < 4; i++)
#pragma unroll
        for (int p = 0; p < 4; p++) acc2[i][p] = 0ull;

#pragma unroll 4
    for (int k = 0; k < 96; k++) {
        float4 wv = *(const float4*)(g_wtA + k * 384 + j0);
        ull w0 = pack2(wv.x, wv.x), w1 = pack2(wv.y, wv.y);
        ull w2 = pack2(wv.z, wv.z), w3 = pack2(wv.w, wv.w);
        ulonglong2 xa = *(const ulonglong2*)(xrow + k * 36);
        ulonglong2 xb = *(const ulonglong2*)(xrow + k * 36 + 4);
        acc2[0][0] = fma2(xa.x, w0, acc2[0][0]); acc2[0][1] = fma2(xa.y, w0, acc2[0][1]);
        acc2[0][2] = fma2(xb.x, w0, acc2[0][2]); acc2[0][3] = fma2(xb.y, w0, acc2[0][3]);
        acc2[1][0] = fma2(xa.x, w1, acc2[1][0]); acc2[1][1] = fma2(xa.y, w1, acc2[1][1]);
        acc2[1][2] = fma2(xb.x, w1, acc2[1][2]); acc2[1][3] = fma2(xb.y, w1, acc2[1][3]);
        acc2[2][0] = fma2(xa.x, w2, acc2[2][0]); acc2[2][1] = fma2(xa.y, w2, acc2[2][1]);
        acc2[2][2] = fma2(xb.x, w2, acc2[2][2]); acc2[2][3] = fma2(xb.y, w2, acc2[2][3]);
        acc2[3][0] = fma2(xa.x, w3, acc2[3][0]); acc2[3][1] = fma2(xa.y, w3, acc2[3][1]);
        acc2[3][2] = fma2(xb.x, w3, acc2[3][2]); acc2[3][3] = fma2(xb.y, w3, acc2[3][3]);
    }
    __syncthreads();

    if (j0 < DI) {
#pragma unroll
        for (int jj = 0; jj < 4; jj++) {
            float* dst = g_x1 + ((size_t)b * DI + j0 + jj) * LL + l0 + lo * 8;
            float2 a0 = unpack2(acc2[jj][0]), a1 = unpack2(acc2[jj][1]);
            float2 a2 = unpack2(acc2[jj][2]), a3 = unpack2(acc2[jj][3]);
            *(float4*)dst       = make_float4(a0.x, a0.y, a1.x, a1.y);
            *(float4*)(dst + 4) = make_float4(a2.x, a2.y, a3.x, a3.y);
        }
    } else {
        int d0 = j0 - DI;
#pragma unroll
        for (int jj = 0; jj < 4; jj++) {
#pragma unroll
            for (int p = 0; p < 4; p++) {
                float2 v = unpack2(acc2[jj][p]);
                zs[(lo * 8 + 2 * p + 0) * DI + d0 + jj] = v.x;
                zs[(lo * 8 + 2 * p + 1) * DI + d0 + jj] = v.y;
            }
        }
    }
    __syncthreads();
    float4* zdst = (float4*)(g_z + ((size_t)b * LL + l0) * DI);
    const float4* zsrc = (const float4*)zs;
#pragma unroll
    for (int r = 0; r < 4; r++) zdst[tid + 384 * r] = zsrc[tid + 384 * r];
}

// ---------------- K23: fused depthwise convs, plane split into 2 halves ----------------
__global__ void __launch_bounds__(256) k23_conv(const float* __restrict__ cw1,
                                                const float* __restrict__ cb1,
                                                const float* __restrict__ cw2,
                                                const float* __restrict__ cb2) {
    __shared__ __align__(16) float s_in [36 * 64];
    __shared__ __align__(16) float s_mid[34 * 64];
    __shared__ float w1[9], w2[9], bb1, bb2;
    int plane = blockIdx.x >> 1;
    int half  = blockIdx.x & 1;
    int h0 = half * 32;
    int c = plane % DI;
    int tid = threadIdx.x;
    if (tid < 9)        w1[tid]     = cw1[c * 9 + tid];
    else if (tid < 18)  w2[tid - 9] = cw2[c * 9 + tid - 9];
    else if (tid == 18) bb1 = cb1[c];
    else if (tid == 19) bb2 = cb2[c];

    const float* src = g_x1 + (size_t)plane * LL;
    for (int i = tid; i < 576; i += 256) {
        int r = i >> 4, c4 = i & 15;
        int gr = h0 - 2 + r;
        float4 v = make_float4(0.f, 0.f, 0.f, 0.f);
        if (gr >= 0 && gr < 64) v = *(const float4*)(src + gr * 64 + c4 * 4);
        *(float4*)&s_in[r * 64 + c4 * 4] = v;
    }
    __syncthreads();

    int w = tid & 63, q = tid >> 6;
    float* dst1 = g_xs + (size_t)plane * LT + CC;
    int wl = (w > 0) ? 1 : 0, wr = (w < 63) ? 1 : 0;
    for (int r = 0; r < 9; r++) {
        int mi = q * 9 + r;
        if (mi >= 34) break;
        int gm = h0 - 1 + mi;
        float val = 0.f;
        if (gm >= 0 && gm < 64) {
            float s = bb1;
#pragma unroll
            for (int kh = 0; kh < 3; kh++) {
                const float* row = s_in + (mi + kh) * 64 + w;
                float acc = w1[kh * 3 + 1] * row[0];
                if (wl) acc += w1[kh * 3 + 0] * row[-1];
                if (wr) acc += w1[kh * 3 + 2] * row[1];
                s += acc;
            }
            val = silu_f(s);
            if (gm >= h0 && gm < h0 + 32)
                dst1[gm * 64 + w] = val;
        }
        s_mid[mi * 64 + w] = val;
    }
    __syncthreads();

    int ow = tid & 31;
    int oq = tid >> 5;
    float* dst2 = g_dxc + (size_t)plane * 1024;
#pragma unroll
    for (int r = 0; r < 2; r++) {
        int ohl = oq * 2 + r;
        int oh  = half * 16 + ohl;
        float s = bb2;
#pragma unroll
        for (int kh = 0; kh < 3; kh++) {
            const float* mrow = s_mid + (2 * ohl + kh) * 64;
#pragma unroll
            for (int kw = 0; kw < 3; kw++) {
                int iw = 2 * ow + kw - 1;
                if (iw < 0 || iw >= 64) continue;
                s += w2[kh * 3 + kw] * mrow[iw];
            }
        }
        dst2[oh * 32 + ow] = s;
    }
}

// ---------------- K4a: depth_fc K-split GEMM (frozen) ----------------
__global__ void __launch_bounds__(192) k4a_fc() {
    __shared__ __align__(16) float sXt[KCHUNK * 20];
    __shared__ __align__(16) float sWt[16 * 196];
    int m0 = blockIdx.x * MTILE;
    int ks = blockIdx.y;
    int k0 = ks * KCHUNK;
    int tid = threadIdx.x;
    int dq = tid % 48, mq = tid / 48;

    if (tid < MTILE * (KCHUNK / 4)) {
        int m = tid >> 3, c4 = tid & 7;
        float4 v = *(const float4*)(g_dxc + (size_t)(m0 + m) * 1024 + k0 + c4 * 4);
        sXt[(c4 * 4 + 0) * 20 + m] = v.x;
        sXt[(c4 * 4 + 1) * 20 + m] = v.y;
        sXt[(c4 * 4 + 2) * 20 + m] = v.z;
        sXt[(c4 * 4 + 3) * 20 + m] = v.w;
    }

    ull acc2[4][2];
#pragma unroll
    for (int i = 0; i < 4; i++) { acc2[i][0] = 0ull; acc2[i][1] = 0ull; }

#pragma unroll
    for (int s = 0; s < KCHUNK / 16; s++) {
        __syncthreads();
#pragma unroll
        for (int j = 0; j < 4; j++) {
            int q4 = tid + 192 * j;
            int row = q4 / 48, col = q4 % 48;
            float4 v = *(const float4*)(g_wfcT + (size_t)(k0 + s * 16 + row) * DI + col * 4);
            *(float4*)&sWt[row * 196 + col * 4] = v;
        }
        __syncthreads();
        ulonglong2 wc = *(const ulonglong2*)&sWt[0 * 196 + dq * 4];
        float4     xc = *(const float4*)&sXt[(s * 16 + 0) * 20 + mq * 4];
#pragma unroll
        for (int k = 0; k < 16; k++) {
            ulonglong2 wn;
            float4 xn;
            if (k < 15) {
                wn = *(const ulonglong2*)&sWt[(k + 1) * 196 + dq * 4];
                xn = *(const float4*)&sXt[(s * 16 + k + 1) * 20 + mq * 4];
            }
            ull xm0 = pack2(xc.x, xc.x);
            ull xm1 = pack2(xc.y, xc.y);
            ull xm2 = pack2(xc.z, xc.z);
            ull xm3 = pack2(xc.w, xc.w);
            acc2[0][0] = fma2(wc.x, xm0, acc2[0][0]); acc2[0][1] = fma2(wc.y, xm0, acc2[0][1]);
            acc2[1][0] = fma2(wc.x, xm1, acc2[1][0]); acc2[1][1] = fma2(wc.y, xm1, acc2[1][1]);
            acc2[2][0] = fma2(wc.x, xm2, acc2[2][0]); acc2[2][1] = fma2(wc.y, xm2, acc2[2][1]);
            acc2[3][0] = fma2(wc.x, xm3, acc2[3][0]); acc2[3][1] = fma2(wc.y, xm3, acc2[3][1]);
            if (k < 15) { wc = wn; xc = xn; }
        }
    }

    float* pb = g_fcp + ((size_t)ks * BB * DI + m0 + mq * 4) * DI + dq * 4;
#pragma unroll
    for (int m = 0; m < 4; m++) {
        float2 a = unpack2(acc2[m][0]);
        float2 bq = unpack2(acc2[m][1]);
        *(float4*)(pb + (size_t)m * DI) = make_float4(a.x, a.y, bq.x, bq.y);
    }
}

// ---------------- K4b: reduce 32 partials + bias + SiLU ----------------
__global__ void __launch_bounds__(192) k4b_fc(const float* __restrict__ fcb) {
    int m = blockIdx.x;
    int d = threadIdx.x;
    int b = m / DI, lp = m % DI;
    float s = fcb[d];
    const float* p = g_fcp + (size_t)m * DI + d;
#pragma unroll
    for (int ks = 0; ks < KSPLIT; ks++) {
        s += p[(size_t)ks * BB * DI * DI];
    }
    g_xs[((size_t)b * DI + d) * LT + lp] = silu_f(s);
}

// ---------------- K5: x_proj + dt proj + softplus ----------------
__global__ void __launch_bounds__(256) k5_xproj(const float* __restrict__ dtw,
                                                const float* __restrict__ dtb) {
    __shared__ __align__(16) float s_u[DI * 32];
    __shared__ __align__(16) float sxd[38 * 36];
    __shared__ __align__(16) float s_dtw[DI * RK];
    __shared__ float s_dtb[DI];
    int tid = threadIdx.x;
    int b   = blockIdx.y;
    int l0  = blockIdx.x * 32;

    for (int i = tid; i < DI * 8; i += 256) {
        int d = i >> 3, c4 = i & 7;
        ((float4*)s_u)[d * 8 + c4] =
            *(const float4*)(g_xs + ((size_t)b * DI + d) * LT + l0 + c4 * 4);
    }
    for (int i = tid; i < DI * RK; i += 256) s_dtw[i] = dtw[i];
    if (tid < DI) s_dtb[tid] = dtb[tid];
    __syncthreads();

    if (tid < 152) {
        int cp = tid >> 3, lq = tid & 7;
        int c0 = 2 * cp;
        ull a0 = 0ull, a1 = 0ull, b0 = 0ull, b1 = 0ull;
#pragma unroll 4
        for (int d = 0; d < DI; d++) {
            ulonglong2 uv = *(const ulonglong2*)&s_u[d * 32 + lq * 4];
            ull xp2 = *(const ull*)&g_xpT[d * 40 + c0];
            float2 xf = unpack2(xp2);
            ull x0p = pack2(xf.x, xf.x), x1p = pack2(xf.y, xf.y);
            a0 = fma2(uv.x, x0p, a0); a1 = fma2(uv.y, x0p, a1);
            b0 = fma2(uv.x, x1p, b0); b1 = fma2(uv.y, x1p, b1);
        }
        float2 r0 = unpack2(a0), r1 = unpack2(a1);
        *(float4*)&sxd[c0 * 36 + lq * 4] = make_float4(r0.x, r0.y, r1.x, r1.y);
        float2 s0 = unpack2(b0), s1 = unpack2(b1);
        *(float4*)&sxd[(c0 + 1) * 36 + lq * 4] = make_float4(s0.x, s0.y, s1.x, s1.y);
    }
    __syncthreads();

    {
        int n = tid & 15;
        int lh = tid >> 4;
        if (lh < 16) {
#pragma unroll
            for (int rr = 0; rr < 2; rr++) {
                int l = lh + rr * 16;
                g_bc[((size_t)b * LT + l0 + l) * DSN + n] =
                    make_float2(sxd[(RK + n) * 36 + l], sxd[(RK + DSN + n) * 36 + l]);
            }
        }
    }

    const float L2E = 1.4426950408889634f;
    for (int item = tid; item < DI * 8; item += 256) {
        int d = item >> 3, lq = item & 7;
        float dt0 = s_dtb[d], dt1 = dt0, dt2 = dt0, dt3 = dt0;
#pragma unroll
        for (int r = 0; r < RK; r++) {
            float w = s_dtw[d * RK + r];
            float4 xv = *(const float4*)&sxd[r * 36 + lq * 4];
            dt0 += w * xv.x; dt1 += w * xv.y; dt2 += w * xv.z; dt3 += w * xv.w;
        }
        float del[4]; float dts[4] = {dt0, dt1, dt2, dt3};
#pragma unroll
        for (int j = 0; j < 4; j++) {
            float dt = dts[j];
            if (dt > 20.f)       del[j] = dt;
            else if (dt < -20.f) del[j] = __expf(dt);
            else                 del[j] = log1pf(__expf(dt));
        }
        float4 uv = *(const float4*)&s_u[d * 32 + lq * 4];
        float2* qd = g_q2 + ((size_t)b * DI + d) * LT + l0 + lq * 4;
        *(float4*)qd       = make_float4(del[0] * L2E, del[0] * uv.x, del[1] * L2E, del[1] * uv.y);
        *(float4*)(qd + 2) = make_float4(del[2] * L2E, del[2] * uv.z, del[3] * L2E, del[3] * uv.w);
    }
}

// ---------------- K6: fused scan, decoupled lookback with batched prefetch ----------------
__global__ void __launch_bounds__(128) k6_scan(const float* __restrict__ dsv) {
    __shared__ __align__(16) float2 s_q[16][CL];
    __shared__ __align__(16) float2 s_bc[CL][DSN];
    int dg = blockIdx.x % 12;
    int c  = blockIdx.x / 12;
    int b  = blockIdx.y;
    int t  = threadIdx.x;
    int l0 = c * CL;

    {
        int dl = t >> 3, j = t & 7;
        const float2* src = g_q2 + (size_t)(b * DI + dg * 16 + dl) * LT + l0;
        for (int k = j; k < CL; k += 8) s_q[dl][k] = src[k];
    }
    {
        const float4* src = (const float4*)(g_bc + ((size_t)b * LT + l0) * DSN);
        float4* dst = (float4*)&s_bc[0][0];
        for (int i = t; i < CL * DSN / 2; i += 128) dst[i] = src[i];
    }
    __syncthreads();

    int w = t >> 5, lane = t & 31;
    int dgrp = lane >> 3, n = lane & 7;
    int dw = w * 4 + dgrp;
    int d  = dg * 16 + dw;
    int g  = b * DI + d;
    float An0 = g_An[d * DSN + n];
    float An1 = g_An[d * DSN + n + 8];

    // ---- pass 1: local aggregates ----
    float h0 = 0.f, P0 = 1.f, h1 = 0.f, P1 = 1.f;
#pragma unroll 2
    for (int l = 0; l < CL; l++) {
        float2 qq = s_q[dw][l];
        float bx = s_bc[l][n].x;
        float b1x = s_bc[l][n + 8].x;
        float a0 = ex2(qq.x * An0);
        float a1 = ex2(qq.x * An1);
        P0 *= a0; h0 = a0 * h0 + qq.y * bx;
        P1 *= a1; h1 = a1 * h1 + qq.y * b1x;
    }
    int idx = (g * NC + c) * DSN + n;
    g_hend[idx]     = h0; g_P[idx]     = P0;
    g_hend[idx + 8] = h1; g_P[idx + 8] = P1;
    __threadfence();
    __syncthreads();
    int fbase = (b * 12 + dg) * NC;
    if (t == 0) atomicExch(&g_flag[fbase + c], 1);

    // ---- lookback (batched prefetch: 8 chunks of independent loads, then combine) ----
    float hp0 = 0.f, hp1 = 0.f;
    if (c > 0) {
        if (t == 0) {
            volatile int* vf = g_flag;
            for (int cc = 0; cc < c; cc++)
                while (vf[fbase + cc] == 0) { }
        }
        __syncthreads();
        for (int cc0 = 0; cc0 < c; cc0 += 8) {
            int nb = c - cc0; if (nb > 8) nb = 8;
            float Pa[8], Ha[8], Pb[8], Hb[8];
            for (int j = 0; j < nb; j++) {
                int ix = (g * NC + cc0 + j) * DSN + n;
                Pa[j] = __ldcg(&g_P[ix]);     Ha[j] = __ldcg(&g_hend[ix]);
                Pb[j] = __ldcg(&g_P[ix + 8]); Hb[j] = __ldcg(&g_hend[ix + 8]);
            }
            for (int j = 0; j < nb; j++) {
                hp0 = Pa[j] * hp0 + Ha[j];
                hp1 = Pb[j] * hp1 + Hb[j];
            }
        }
    }

    // ---- pass 2: outputs ----
    float ds = dsv[d];
    const float* urow = g_xs + (size_t)g * LT + l0;
    h0 = hp0; h1 = hp1;
#pragma unroll 2
    for (int l = 0; l < CL; l++) {
        float2 qq = s_q[dw][l];
        float2 bv0 = s_bc[l][n];
        float2 bv1 = s_bc[l][n + 8];
        float a0 = ex2(qq.x * An0);
        float a1 = ex2(qq.x * An1);
        h0 = a0 * h0 + qq.y * bv0.x;
        h1 = a1 * h1 + qq.y * bv1.x;
        float pr = h0 * bv0.y + h1 * bv1.y;
        pr += __shfl_xor_sync(0xffffffffu, pr, 1);
        pr += __shfl_xor_sync(0xffffffffu, pr, 2);
        pr += __shfl_xor_sync(0xffffffffu, pr, 4);
        int lg = l0 + l;
        if (n == 0 && lg >= CC) {
            g_yt[((size_t)b * LL + (lg - CC)) * DI + d] = pr + ds * urow[l];
        }
    }
}

// ---------------- K7: LN + gate + out_proj ----------------
__global__ void __launch_bounds__(192) k7_out(const float* __restrict__ onw,
                                              const float* __restrict__ onb,
                                              float* __restrict__ out) {
    __shared__ __align__(16) float sy [8 * DI];
    __shared__ __align__(16) float sgv[DI * 10];
    __shared__ __align__(16) float2 sr2[3][48][8];
    __shared__ float smu[8], srs[8];
    int b   = blockIdx.y;
    int l0  = blockIdx.x * 8;
    int tid = threadIdx.x;
    int lane = tid & 31, w = tid >> 5;

    const float4* ysrc = (const float4*)(g_yt + ((size_t)b * LL + l0) * DI);
    float4* syd = (float4*)sy;
#pragma unroll
    for (int i = 0; i < 2; i++) syd[tid + 192 * i] = ysrc[tid + 192 * i];
    __syncthreads();

#pragma unroll
    for (int pass = 0; pass < 2; pass++) {
        int l = pass * 6 + w;
        if (l < 8) {
            float s1 = 0.f, s2 = 0.f;
#pragma unroll
            for (int k = 0; k < 6; k++) {
                float v = sy[l * DI + lane + 32 * k];
                s1 += v; s2 += v * v;
            }
#pragma unroll
            for (int o = 16; o > 0; o >>= 1) {
                s1 += __shfl_xor_sync(0xffffffffu, s1, o);
                s2 += __shfl_xor_sync(0xffffffffu, s2, o);
            }
            if (lane == 0) {
                float mu = s1 * (1.f / 192.f);
                smu[l] = mu;
                srs[l] = rsqrtf(s2 * (1.f / 192.f) - mu * mu + 1e-5f);
            }
        }
    }
    __syncthreads();

    float wn = onw[tid], bn = onb[tid];
    const float* zr = g_z + ((size_t)b * LL + l0) * DI + tid;
#pragma unroll
    for (int l = 0; l < 8; l++) {
        float y  = sy[l * DI + tid];
        float yn = (y - smu[l]) * srs[l] * wn + bn;
        float zv = zr[(size_t)l * DI];
        sgv[tid * 10 + l] = yn * silu_f(zv);
    }
    __syncthreads();

    int oo = tid % 48, q = tid / 48;
    int o0 = oo * 2;
    int dbase = q * 48;
    ull acc2[2][4] = {{0ull,0ull,0ull,0ull},{0ull,0ull,0ull,0ull}};
#pragma unroll 4
    for (int i = 0; i < 48; i++) {
        int d = dbase + i;
        float2 wf = *(const float2*)&g_wtO[d * DM + o0];
        ull w0 = pack2(wf.x, wf.x), w1 = pack2(wf.y, wf.y);
        const ull* gp = (const ull*)&sgv[d * 10];
        acc2[0][0] = fma2(gp[0], w0, acc2[0][0]);
        acc2[0][1] = fma2(gp[1], w0, acc2[0][1]);
        acc2[0][2] = fma2(gp[2], w0, acc2[0][2]);
        acc2[0][3] = fma2(gp[3], w0, acc2[0][3]);
        acc2[1][0] = fma2(gp[0], w1, acc2[1][0]);
        acc2[1][1] = fma2(gp[1], w1, acc2[1][1]);
        acc2[1][2] = fma2(gp[2], w1, acc2[1][2]);
        acc2[1][3] = fma2(gp[3], w1, acc2[1][3]);
    }
    if (q > 0) {
#pragma unroll
        for (int p = 0; p < 4; p++) {
            float2 a = unpack2(acc2[0][p]);
            float2 bq = unpack2(acc2[1][p]);
            sr2[q - 1][oo][2 * p + 0] = make_float2(a.x, bq.x);
            sr2[q - 1][oo][2 * p + 1] = make_float2(a.y, bq.y);
        }
    }
    __syncthreads();
    if (q == 0) {
#pragma unroll
        for (int p = 0; p < 4; p++) {
            float2 a = unpack2(acc2[0][p]);
            float2 bq = unpack2(acc2[1][p]);
            float2 r0 = make_float2(a.x, bq.x);
            float2 r1 = make_float2(a.y, bq.y);
#pragma unroll
            for (int qq = 0; qq < 3; qq++) {
                float2 s0 = sr2[qq][oo][2 * p + 0];
                float2 s1 = sr2[qq][oo][2 * p + 1];
                r0.x += s0.x; r0.y += s0.y;
                r1.x += s1.x; r1.y += s1.y;
            }
            *(float2*)&out[((size_t)b * LL + l0 + 2 * p + 0) * DM + o0] = r0;
            *(float2*)&out[((size_t)b * LL + l0 + 2 * p + 1) * DM + o0] = r1;
        }
    }
}

// ---------------- launch ----------------
extern "C" void kernel_launch(void* const* d_in, const int* in_sizes, int n_in,
                              void* d_out, int out_size) {
    const float* x            = (const float*)d_in[0];
    const float* in_proj_w    = (const float*)d_in[1];
    const float* conv2d_w     = (const float*)d_in[2];
    const float* conv2d_b     = (const float*)d_in[3];
    const float* depth_conv_w = (const float*)d_in[4];
    const float* depth_conv_b = (const float*)d_in[5];
    const float* depth_fc_w   = (const float*)d_in[6];
    const float* depth_fc_b   = (const float*)d_in[7];
    const float* x_proj_w     = (const float*)d_in[8];
    const float* dt_projs_w   = (const float*)d_in[9];
    const float* dt_projs_b   = (const float*)d_in[10];
    const float* A_logs       = (const float*)d_in[11];
    const float* Ds           = (const float*)d_in[12];
    const float* out_norm_w   = (const float*)d_in[13];
    const float* out_norm_b   = (const float*)d_in[14];
    const float* out_proj_w   = (const float*)d_in[15];
    float* out = (float*)d_out;

    k0_prep<<<480, 256>>>(in_proj_w, out_proj_w, A_logs, x_proj_w, depth_fc_w);
    k1_inproj<<<dim3(LL / 32, BB), 384>>>(x);
    k23_conv<<<BB * DI * 2, 256>>>(conv2d_w, conv2d_b, depth_conv_w, depth_conv_b);
    k4a_fc<<<dim3(BB * DI / MTILE, KSPLIT), 192>>>();
    k4b_fc<<<BB * DI, 192>>>(depth_fc_b);
    k5_xproj<<<dim3(LT / 32, BB), 256>>>(dt_projs_w, dt_projs_b);
    k6_scan<<<dim3(12 * NC, BB), 128>>>(Ds);
    k7_out<<<dim3(LL / 8, BB), 192>>>(out_norm_w, out_norm_b, out);
}